// round 4
// baseline (speedup 1.0000x reference)
#include <cuda_runtime.h>
#include <cuda_bf16.h>
#include <cstdint>

#define SEQ    2048
#define DMODEL 2048
#define NHEAD  8
#define HD     256
#define BATCH  2
#define BH     (BATCH*NHEAD)
#define ROWS   (BATCH*SEQ)          // 4096

typedef __nv_bfloat16 bf16;

// ---------------- scratch (device globals; alloc-guard compliant) ----------------
__device__ __align__(256) bf16 s_xhi[(size_t)ROWS*DMODEL],    s_xlo[(size_t)ROWS*DMODEL];
__device__ __align__(256) bf16 s_wqhi[(size_t)DMODEL*DMODEL], s_wqlo[(size_t)DMODEL*DMODEL];
__device__ __align__(256) bf16 s_wkhi[(size_t)HD*DMODEL],     s_wklo[(size_t)HD*DMODEL];
__device__ __align__(256) bf16 s_wvhi[(size_t)HD*DMODEL],     s_wvlo[(size_t)HD*DMODEL];
__device__ __align__(256) bf16 s_wohi[(size_t)DMODEL*DMODEL], s_wolo[(size_t)DMODEL*DMODEL];
__device__ __align__(256) bf16 s_qhi[(size_t)ROWS*DMODEL],    s_qlo[(size_t)ROWS*DMODEL];
__device__ __align__(256) bf16 s_khi[(size_t)ROWS*HD],        s_klo[(size_t)ROWS*HD];
__device__ __align__(256) bf16 s_vthi[(size_t)BATCH*HD*SEQ],  s_vtlo[(size_t)BATCH*HD*SEQ];
__device__ __align__(256) bf16 s_phi[(size_t)BH*SEQ*SEQ],     s_plo[(size_t)BH*SEQ*SEQ];
__device__ __align__(256) bf16 s_ahi[(size_t)ROWS*DMODEL],    s_alo[(size_t)ROWS*DMODEL];
__device__ __align__(16) float g_q[(size_t)ROWS*DMODEL];
__device__ __align__(16) float g_k[(size_t)ROWS*HD];
__device__ __align__(16) float g_v[(size_t)ROWS*HD];

// ---------------- helpers ----------------
__device__ __forceinline__ uint32_t smem_u32(const void* p) {
    uint32_t a;
    asm("{ .reg .u64 t; cvta.to.shared.u64 t, %1; cvt.u32.u64 %0, t; }" : "=r"(a) : "l"(p));
    return a;
}
#define SWZ(o) ((o) ^ (((o) >> 3) & 0x70))

__device__ __forceinline__ void cp16(uint32_t saddr, const void* gaddr) {
    asm volatile("cp.async.cg.shared.global [%0], [%1], 16;" :: "r"(saddr), "l"(gaddr));
}
__device__ __forceinline__ void cp_commit() { asm volatile("cp.async.commit_group;"); }
template<int N> __device__ __forceinline__ void cp_wait() {
    asm volatile("cp.async.wait_group %0;" :: "n"(N));
}
__device__ __forceinline__ void ldsm4(uint32_t* r, uint32_t addr) {
    asm volatile("ldmatrix.sync.aligned.m8n8.x4.shared.b16 {%0,%1,%2,%3}, [%4];"
                 : "=r"(r[0]), "=r"(r[1]), "=r"(r[2]), "=r"(r[3]) : "r"(addr));
}
__device__ __forceinline__ void mma16816(float* c, const uint32_t* a, const uint32_t* b) {
    asm volatile(
        "mma.sync.aligned.m16n8k16.row.col.f32.bf16.bf16.f32 "
        "{%0,%1,%2,%3}, {%4,%5,%6,%7}, {%8,%9}, {%0,%1,%2,%3};"
        : "+f"(c[0]), "+f"(c[1]), "+f"(c[2]), "+f"(c[3])
        : "r"(a[0]), "r"(a[1]), "r"(a[2]), "r"(a[3]), "r"(b[0]), "r"(b[1]));
}

// ---------------- HMMA GEMM: C[M,N] = alpha * A[M,K] @ B[N,K]^T, bf16 hi/lo 3-product ----
#define BM 128
#define BN 128
#define BK 64
#define STG_A_HI 0
#define STG_A_LO 16384
#define STG_B_HI 32768
#define STG_B_LO 49152
#define STG_STRIDE 65536
#define SMEM_BYTES (2*STG_STRIDE)   // 131072

extern __shared__ char dynsmem[];

__device__ __forceinline__ void load_stage(
    uint32_t st, int tid, int k0, int rowBase, int colBase,
    const bf16* ahi, const bf16* alo, int lda,
    const bf16* bhi, const bf16* blo, int ldb)
{
#pragma unroll
    for (int i = 0; i < 4; i++) {
        int idx = tid + i * 256;
        int r = idx >> 3, ch = idx & 7;
        uint32_t so = SWZ((uint32_t)(r * 128 + ch * 16));
        const size_t ao = (size_t)(rowBase + r) * lda + k0 + ch * 8;
        const size_t bo = (size_t)(colBase + r) * ldb + k0 + ch * 8;
        cp16(st + STG_A_HI + so, ahi + ao);
        cp16(st + STG_A_LO + so, alo + ao);
        cp16(st + STG_B_HI + so, bhi + bo);
        cp16(st + STG_B_LO + so, blo + bo);
    }
}

struct Frags {
    uint32_t ah[4][4], al[4][4];
    uint32_t bh[4][2], bl[4][2];
};

__device__ __forceinline__ void load_frags(Frags& f, uint32_t st, int ks,
                                           int warpM, int warpN, int lane)
{
    const int kk = ks * 16 + (lane >> 4) * 8;
#pragma unroll
    for (int mf = 0; mf < 4; mf++) {
        int row = warpM * 64 + mf * 16 + (lane & 15);
        uint32_t addr = st + SWZ((uint32_t)(row * 128 + kk * 2));
        ldsm4(f.ah[mf], addr + STG_A_HI);
        ldsm4(f.al[mf], addr + STG_A_LO);
    }
#pragma unroll
    for (int nb = 0; nb < 2; nb++) {
        int nrow = warpN * 32 + nb * 16 + (lane & 15);
        uint32_t addr = st + SWZ((uint32_t)(nrow * 128 + kk * 2));
        uint32_t t[4];
        ldsm4(t, addr + STG_B_HI);
        f.bh[nb*2][0] = t[0]; f.bh[nb*2][1] = t[2];
        f.bh[nb*2+1][0] = t[1]; f.bh[nb*2+1][1] = t[3];
        ldsm4(t, addr + STG_B_LO);
        f.bl[nb*2][0] = t[0]; f.bl[nb*2][1] = t[2];
        f.bl[nb*2+1][0] = t[1]; f.bl[nb*2+1][1] = t[3];
    }
}

// EPI 0: fp32 C (scaled by alpha).  EPI 1: bf16 hi/lo plane outputs.
template<int EPI>
__device__ void hmma_gemm(const bf16* __restrict__ ahi, const bf16* __restrict__ alo, int lda,
                          const bf16* __restrict__ bhi, const bf16* __restrict__ blo, int ldb,
                          float* __restrict__ C, bf16* __restrict__ Chi, bf16* __restrict__ Clo,
                          int ldc, int K, float alpha)
{
    const uint32_t sb = smem_u32(dynsmem);
    const int tid = threadIdx.x;
    const int lane = tid & 31, wid = tid >> 5;
    const int warpM = wid >> 2, warpN = wid & 3;     // 2 x 4 warp grid
    const int rowBase = blockIdx.y * BM, colBase = blockIdx.x * BN;

    float acc[4][4][4];
#pragma unroll
    for (int mf = 0; mf < 4; mf++)
#pragma unroll
        for (int nf = 0; nf < 4; nf++)
#pragma unroll
            for (int c = 0; c < 4; c++) acc[mf][nf][c] = 0.f;

    const int KI = K / BK;
    load_stage(sb, tid, 0, rowBase, colBase, ahi, alo, lda, bhi, blo, ldb);
    cp_commit();
    load_stage(sb + STG_STRIDE, tid, BK, rowBase, colBase, ahi, alo, lda, bhi, blo, ldb);
    cp_commit();

    Frags fr[2];
    for (int it = 0; it < KI; it++) {
        cp_wait<1>();
        __syncthreads();
        const uint32_t st = sb + (it & 1) * STG_STRIDE;

        load_frags(fr[0], st, 0, warpM, warpN, lane);
#pragma unroll
        for (int ks = 0; ks < 4; ks++) {
            Frags& f = fr[ks & 1];
            if (ks < 3) load_frags(fr[(ks + 1) & 1], st, ks + 1, warpM, warpN, lane);
            // product-major: 16 independent accs between same-acc reuses
#pragma unroll
            for (int mf = 0; mf < 4; mf++)
#pragma unroll
                for (int nf = 0; nf < 4; nf++) mma16816(acc[mf][nf], f.ah[mf], f.bh[nf]);
#pragma unroll
            for (int mf = 0; mf < 4; mf++)
#pragma unroll
                for (int nf = 0; nf < 4; nf++) mma16816(acc[mf][nf], f.ah[mf], f.bl[nf]);
#pragma unroll
            for (int mf = 0; mf < 4; mf++)
#pragma unroll
                for (int nf = 0; nf < 4; nf++) mma16816(acc[mf][nf], f.al[mf], f.bh[nf]);
        }
        __syncthreads();
        if (it + 2 < KI)
            load_stage(sb + (it & 1) * STG_STRIDE, tid, (it + 2) * BK,
                       rowBase, colBase, ahi, alo, lda, bhi, blo, ldb);
        cp_commit();
    }
    cp_wait<0>();

#pragma unroll
    for (int mf = 0; mf < 4; mf++) {
        int row0 = rowBase + warpM * 64 + mf * 16 + (lane >> 2);
#pragma unroll
        for (int nf = 0; nf < 4; nf++) {
            int col = colBase + warpN * 32 + nf * 8 + (lane & 3) * 2;
            if (EPI == 0) {
                float2 v0 = {alpha * acc[mf][nf][0], alpha * acc[mf][nf][1]};
                float2 v1 = {alpha * acc[mf][nf][2], alpha * acc[mf][nf][3]};
                *(float2*)(C + (size_t)row0 * ldc + col) = v0;
                *(float2*)(C + (size_t)(row0 + 8) * ldc + col) = v1;
            } else {
#pragma unroll
                for (int half = 0; half < 2; half++) {
                    size_t o = (size_t)(row0 + half * 8) * ldc + col;
                    float v0 = acc[mf][nf][half * 2], v1 = acc[mf][nf][half * 2 + 1];
                    bf16 h0 = __float2bfloat16(v0), h1 = __float2bfloat16(v1);
                    bf16 l0 = __float2bfloat16(v0 - __bfloat162float(h0));
                    bf16 l1 = __float2bfloat16(v1 - __bfloat162float(h1));
                    uint32_t hp = (uint32_t)__bfloat16_as_ushort(h0) | ((uint32_t)__bfloat16_as_ushort(h1) << 16);
                    uint32_t lp = (uint32_t)__bfloat16_as_ushort(l0) | ((uint32_t)__bfloat16_as_ushort(l1) << 16);
                    *(uint32_t*)(Chi + o) = hp;
                    *(uint32_t*)(Clo + o) = lp;
                }
            }
        }
    }
}

// ---------------- GEMM wrappers ----------------
__global__ __launch_bounds__(256, 1) void k_gemm_plain(
    const bf16* ahi, const bf16* alo, int lda,
    const bf16* bhi, const bf16* blo, int ldb,
    float* C, int ldc, int K, float alpha)
{
    hmma_gemm<0>(ahi, alo, lda, bhi, blo, ldb, C, nullptr, nullptr, ldc, K, alpha);
}

__global__ __launch_bounds__(256, 1) void k_gemm_scores(
    const bf16* qhi, const bf16* qlo, const bf16* khi, const bf16* klo, float* W)
{
    if (blockIdx.x > blockIdx.y) return;     // causal: fully-masked tile
    const int bh = blockIdx.z, b = bh / NHEAD, h = bh % NHEAD;
    size_t qa = (size_t)b * SEQ * DMODEL + (size_t)h * HD;
    size_t ka = (size_t)b * SEQ * HD;
    hmma_gemm<0>(qhi + qa, qlo + qa, DMODEL, khi + ka, klo + ka, HD,
                 W + (size_t)bh * SEQ * SEQ, nullptr, nullptr, SEQ, HD, 0.0625f);
}

__global__ __launch_bounds__(256, 1) void k_gemm_pv(
    const bf16* phi, const bf16* plo, const bf16* vthi, const bf16* vtlo,
    bf16* ahi_out, bf16* alo_out)
{
    const int bh = blockIdx.z, b = bh / NHEAD, h = bh % NHEAD;
    size_t pa = (size_t)bh * SEQ * SEQ;
    size_t va = (size_t)b * HD * SEQ;
    int kmax = (blockIdx.y + 1) * BM;        // causal clamp
    size_t co = (size_t)b * SEQ * DMODEL + (size_t)h * HD;
    hmma_gemm<1>(phi + pa, plo + pa, SEQ, vthi + va, vtlo + va, SEQ,
                 nullptr, ahi_out + co, alo_out + co, DMODEL, kmax, 1.0f);
}

// ---------------- elementwise fp32 -> bf16 hi/lo split ----------------
__global__ __launch_bounds__(256) void k_cvt(const float4* __restrict__ x,
                                             uint2* __restrict__ hi, uint2* __restrict__ lo, int n4)
{
    int i = blockIdx.x * 256 + threadIdx.x;
    if (i >= n4) return;
    float4 v = x[i];
    bf16 h0 = __float2bfloat16(v.x), h1 = __float2bfloat16(v.y);
    bf16 h2 = __float2bfloat16(v.z), h3 = __float2bfloat16(v.w);
    bf16 g0 = __float2bfloat16(v.x - __bfloat162float(h0));
    bf16 g1 = __float2bfloat16(v.y - __bfloat162float(h1));
    bf16 g2 = __float2bfloat16(v.z - __bfloat162float(h2));
    bf16 g3 = __float2bfloat16(v.w - __bfloat162float(h3));
    uint2 H, L;
    H.x = (uint32_t)__bfloat16_as_ushort(h0) | ((uint32_t)__bfloat16_as_ushort(h1) << 16);
    H.y = (uint32_t)__bfloat16_as_ushort(h2) | ((uint32_t)__bfloat16_as_ushort(h3) << 16);
    L.x = (uint32_t)__bfloat16_as_ushort(g0) | ((uint32_t)__bfloat16_as_ushort(g1) << 16);
    L.y = (uint32_t)__bfloat16_as_ushort(g2) | ((uint32_t)__bfloat16_as_ushort(g3) << 16);
    hi[i] = H;
    lo[i] = L;
}

// ---------------- RoPE (fp32 in) -> bf16 hi/lo planes ----------------
__global__ __launch_bounds__(256) void k_rope_cvt(const int* __restrict__ pos) {
    int idx = blockIdx.x * 256 + threadIdx.x;
    const int total = ROWS * (NHEAD + 1) * 128;
    if (idx >= total) return;
    int j = idx & 127;
    int rest = idx >> 7;
    int slot = rest % (NHEAD + 1);
    int row = rest / (NHEAD + 1);
    float p = (float)pos[row];
    float f = exp2f(-((float)(2 * j) * (1.0f / (float)HD)) * 13.287712379549449f);
    float sv, cv;
    sincosf(p * f, &sv, &cv);
    float x1, x2;
    size_t o;
    if (slot < NHEAD) { o = (size_t)row * DMODEL + slot * HD + j; x1 = g_q[o]; x2 = g_q[o + 128]; }
    else              { o = (size_t)row * HD + j;                 x1 = g_k[o]; x2 = g_k[o + 128]; }
    float y1 = x1 * cv - x2 * sv;
    float y2 = x2 * cv + x1 * sv;
    bf16 h1 = __float2bfloat16(y1), h2 = __float2bfloat16(y2);
    bf16 l1 = __float2bfloat16(y1 - __bfloat162float(h1));
    bf16 l2 = __float2bfloat16(y2 - __bfloat162float(h2));
    if (slot < NHEAD) {
        s_qhi[o] = h1; s_qlo[o] = l1; s_qhi[o + 128] = h2; s_qlo[o + 128] = l2;
    } else {
        s_khi[o] = h1; s_klo[o] = l1; s_khi[o + 128] = h2; s_klo[o + 128] = l2;
    }
}

// ---------------- V transpose + split: g_v[b,k,n] -> vt[b,n,k] ----------------
__global__ void k_vt() {
    __shared__ float t[32][33];
    int b = blockIdx.z;
    int k0 = blockIdx.x * 32, n0 = blockIdx.y * 32;
    int tx = threadIdx.x, ty = threadIdx.y;   // 32 x 8
#pragma unroll
    for (int i = 0; i < 32; i += 8)
        t[ty + i][tx] = g_v[((size_t)(b * SEQ + k0 + ty + i)) * HD + n0 + tx];
    __syncthreads();
#pragma unroll
    for (int i = 0; i < 32; i += 8) {
        float v = t[tx][ty + i];
        bf16 h = __float2bfloat16(v);
        bf16 l = __float2bfloat16(v - __bfloat162float(h));
        size_t o = ((size_t)(b * HD + n0 + ty + i)) * SEQ + k0 + tx;
        s_vthi[o] = h;
        s_vtlo[o] = l;
    }
}

// ---------------- causal softmax (in-place fp32) + bf16 hi/lo plane emit ----------------
__global__ __launch_bounds__(256) void k_softmax(float* __restrict__ w) {
    const int row = blockIdx.x;               // bh*SEQ + q
    const int q = row & (SEQ - 1);
    float* p = w + (size_t)row * SEQ;
    const size_t pb = (size_t)row * SEQ;
    const int len = q + 1;
    const int tid = threadIdx.x;
    __shared__ float red[256];

    float vals[SEQ / 256];
    int cnt = 0;
    float m = -3.4e38f;
    for (int i = tid; i < len; i += 256) {
        float x = p[i];
        vals[cnt++] = x;
        m = fmaxf(m, x);
    }
    red[tid] = m;
    __syncthreads();
#pragma unroll
    for (int s2 = 128; s2 > 0; s2 >>= 1) {
        if (tid < s2) red[tid] = fmaxf(red[tid], red[tid + s2]);
        __syncthreads();
    }
    m = red[0];
    __syncthreads();

    float sum = 0.f;
    for (int c = 0; c < cnt; c++) {
        vals[c] = expf(vals[c] - m);
        sum += vals[c];
    }
    red[tid] = sum;
    __syncthreads();
#pragma unroll
    for (int s2 = 128; s2 > 0; s2 >>= 1) {
        if (tid < s2) red[tid] += red[tid + s2];
        __syncthreads();
    }
    float inv = 1.0f / red[0];

    cnt = 0;
    for (int i = tid; i < len; i += 256) {
        float v = vals[cnt++] * inv;
        p[i] = v;
        bf16 h = __float2bfloat16(v);
        s_phi[pb + i] = h;
        s_plo[pb + i] = __float2bfloat16(v - __bfloat162float(h));
    }
    // fp32 weights: full zero tail (required output)
    for (int i = len + tid; i < SEQ; i += 256) p[i] = 0.0f;
    // bf16 P planes: PV only reads up to the 128-aligned diagonal boundary
    const int kmax = (len + 127) & ~127;
    const bf16 z = __float2bfloat16(0.0f);
    for (int i = len + tid; i < kmax; i += 256) {
        s_phi[pb + i] = z;
        s_plo[pb + i] = z;
    }
}

// ---------------- launch ----------------
static void* sym(const void* s) { void* p = nullptr; cudaGetSymbolAddress(&p, s); return p; }

extern "C" void kernel_launch(void* const* d_in, const int* in_sizes, int n_in,
                              void* d_out, int out_size) {
    const float* hidden = (const float*)d_in[0];
    const int*   pos    = (const int*)d_in[2];
    const float* Wq     = (const float*)d_in[3];
    const float* Wk     = (const float*)d_in[4];
    const float* Wv     = (const float*)d_in[5];
    const float* Wo     = (const float*)d_in[6];

    float* out      = (float*)d_out;
    float* weights  = out + (size_t)ROWS * DMODEL;   // (B, H, S, S)

    cudaFuncSetAttribute(k_gemm_plain,  cudaFuncAttributeMaxDynamicSharedMemorySize, SMEM_BYTES);
    cudaFuncSetAttribute(k_gemm_scores, cudaFuncAttributeMaxDynamicSharedMemorySize, SMEM_BYTES);
    cudaFuncSetAttribute(k_gemm_pv,     cudaFuncAttributeMaxDynamicSharedMemorySize, SMEM_BYTES);

    bf16 *xhi = (bf16*)sym(s_xhi),  *xlo = (bf16*)sym(s_xlo);
    bf16 *wqh = (bf16*)sym(s_wqhi), *wql = (bf16*)sym(s_wqlo);
    bf16 *wkh = (bf16*)sym(s_wkhi), *wkl = (bf16*)sym(s_wklo);
    bf16 *wvh = (bf16*)sym(s_wvhi), *wvl = (bf16*)sym(s_wvlo);
    bf16 *woh = (bf16*)sym(s_wohi), *wol = (bf16*)sym(s_wolo);
    bf16 *qhi = (bf16*)sym(s_qhi),  *qlo = (bf16*)sym(s_qlo);
    bf16 *khi = (bf16*)sym(s_khi),  *klo = (bf16*)sym(s_klo);
    bf16 *vth = (bf16*)sym(s_vthi), *vtl = (bf16*)sym(s_vtlo);
    bf16 *phi = (bf16*)sym(s_phi),  *plo = (bf16*)sym(s_plo);
    bf16 *ahi = (bf16*)sym(s_ahi),  *alo = (bf16*)sym(s_alo);
    float *gq = (float*)sym(g_q), *gk = (float*)sym(g_k);
    float *gv = (float*)sym(g_v);

    // 1. split inputs/weights into bf16 hi/lo planes
    {
        int n4 = ROWS * DMODEL / 4;
        k_cvt<<<(n4 + 255) / 256, 256>>>((const float4*)hidden, (uint2*)xhi, (uint2*)xlo, n4);
        n4 = DMODEL * DMODEL / 4;
        k_cvt<<<(n4 + 255) / 256, 256>>>((const float4*)Wq, (uint2*)wqh, (uint2*)wql, n4);
        k_cvt<<<(n4 + 255) / 256, 256>>>((const float4*)Wo, (uint2*)woh, (uint2*)wol, n4);
        n4 = HD * DMODEL / 4;
        k_cvt<<<(n4 + 255) / 256, 256>>>((const float4*)Wk, (uint2*)wkh, (uint2*)wkl, n4);
        k_cvt<<<(n4 + 255) / 256, 256>>>((const float4*)Wv, (uint2*)wvh, (uint2*)wvl, n4);
    }

    // 2. projections (HMMA)
    k_gemm_plain<<<dim3(DMODEL / BN, ROWS / BM), 256, SMEM_BYTES>>>(xhi, xlo, DMODEL, wqh, wql, DMODEL, gq, DMODEL, DMODEL, 1.0f);
    k_gemm_plain<<<dim3(HD / BN, ROWS / BM),     256, SMEM_BYTES>>>(xhi, xlo, DMODEL, wkh, wkl, DMODEL, gk, HD, DMODEL, 1.0f);
    k_gemm_plain<<<dim3(HD / BN, ROWS / BM),     256, SMEM_BYTES>>>(xhi, xlo, DMODEL, wvh, wvl, DMODEL, gv, HD, DMODEL, 1.0f);

    // 3. RoPE -> bf16 planes ; V transpose -> bf16 planes
    {
        int total = ROWS * (NHEAD + 1) * 128;
        k_rope_cvt<<<(total + 255) / 256, 256>>>(pos);
    }
    k_vt<<<dim3(SEQ / 32, HD / 32, BATCH), dim3(32, 8)>>>();

    // 4. scores (causal tile skip) -> weights fp32 region of d_out
    k_gemm_scores<<<dim3(SEQ / BN, SEQ / BM, BH), 256, SMEM_BYTES>>>(qhi, qlo, khi, klo, weights);

    // 5. softmax in place + emit P bf16 planes
    k_softmax<<<BH * SEQ, 256>>>(weights);

    // 6. P @ V  (causal K clamp) -> bf16 planes for Wo GEMM directly
    k_gemm_pv<<<dim3(HD / BN, SEQ / BM, BH), 256, SMEM_BYTES>>>(phi, plo, vth, vtl, ahi, alo);

    // 7. output projection
    k_gemm_plain<<<dim3(DMODEL / BN, ROWS / BM), 256, SMEM_BYTES>>>(ahi, alo, DMODEL, woh, wol, DMODEL, out, DMODEL, DMODEL, 1.0f);
}

// round 5
// speedup vs baseline: 1.5130x; 1.5130x over previous
#include <cuda_runtime.h>
#include <cuda_bf16.h>
#include <cstdint>

#define SEQ    2048
#define DMODEL 2048
#define NHEAD  8
#define HD     256
#define BATCH  2
#define BH     (BATCH*NHEAD)
#define ROWS   (BATCH*SEQ)          // 4096

typedef __nv_bfloat16 bf16;

// ---------------- scratch (device globals; alloc-guard compliant) ----------------
__device__ __align__(256) bf16 s_xhi[(size_t)ROWS*DMODEL],    s_xlo[(size_t)ROWS*DMODEL];
__device__ __align__(256) bf16 s_wqhi[(size_t)DMODEL*DMODEL], s_wqlo[(size_t)DMODEL*DMODEL];
__device__ __align__(256) bf16 s_wkhi[(size_t)HD*DMODEL],     s_wklo[(size_t)HD*DMODEL];
__device__ __align__(256) bf16 s_wvhi[(size_t)HD*DMODEL],     s_wvlo[(size_t)HD*DMODEL];
__device__ __align__(256) bf16 s_wohi[(size_t)DMODEL*DMODEL], s_wolo[(size_t)DMODEL*DMODEL];
__device__ __align__(256) bf16 s_qhi[(size_t)ROWS*DMODEL],    s_qlo[(size_t)ROWS*DMODEL];
__device__ __align__(256) bf16 s_khi[(size_t)ROWS*HD],        s_klo[(size_t)ROWS*HD];
__device__ __align__(256) bf16 s_vthi[(size_t)BATCH*HD*SEQ],  s_vtlo[(size_t)BATCH*HD*SEQ];
__device__ __align__(256) bf16 s_phi[(size_t)BH*SEQ*SEQ],     s_plo[(size_t)BH*SEQ*SEQ];
__device__ __align__(256) bf16 s_ahi[(size_t)ROWS*DMODEL],    s_alo[(size_t)ROWS*DMODEL];
__device__ __align__(16) float g_q[(size_t)ROWS*DMODEL];
__device__ __align__(16) float g_k[(size_t)ROWS*HD];
__device__ __align__(16) float g_v[(size_t)ROWS*HD];

// ---------------- helpers ----------------
__device__ __forceinline__ uint32_t smem_u32(const void* p) {
    uint32_t a;
    asm("{ .reg .u64 t; cvta.to.shared.u64 t, %1; cvt.u32.u64 %0, t; }" : "=r"(a) : "l"(p));
    return a;
}
#define SWZ(o) ((o) ^ (((o) >> 3) & 0x70))

__device__ __forceinline__ void cp16(uint32_t saddr, const void* gaddr) {
    asm volatile("cp.async.cg.shared.global [%0], [%1], 16;" :: "r"(saddr), "l"(gaddr));
}
__device__ __forceinline__ void cp_commit() { asm volatile("cp.async.commit_group;"); }
template<int N> __device__ __forceinline__ void cp_wait() {
    asm volatile("cp.async.wait_group %0;" :: "n"(N));
}
__device__ __forceinline__ void ldsm4(uint32_t* r, uint32_t addr) {
    asm volatile("ldmatrix.sync.aligned.m8n8.x4.shared.b16 {%0,%1,%2,%3}, [%4];"
                 : "=r"(r[0]), "=r"(r[1]), "=r"(r[2]), "=r"(r[3]) : "r"(addr));
}
__device__ __forceinline__ void mma16816(float* c, const uint32_t* a, const uint32_t* b) {
    asm volatile(
        "mma.sync.aligned.m16n8k16.row.col.f32.bf16.bf16.f32 "
        "{%0,%1,%2,%3}, {%4,%5,%6,%7}, {%8,%9}, {%0,%1,%2,%3};"
        : "+f"(c[0]), "+f"(c[1]), "+f"(c[2]), "+f"(c[3])
        : "r"(a[0]), "r"(a[1]), "r"(a[2]), "r"(a[3]), "r"(b[0]), "r"(b[1]));
}

// ---------------- HMMA GEMM: C[M,N] = alpha * A[M,K] @ B[N,K]^T, bf16 hi/lo 3-product ----
#define BM 128
#define BN 128
#define BK 64
#define STG_A_HI 0
#define STG_A_LO 16384
#define STG_B_HI 32768
#define STG_B_LO 49152
#define STG_STRIDE 65536
#define SMEM_BYTES (2*STG_STRIDE)   // 131072

extern __shared__ char dynsmem[];

__device__ __forceinline__ void load_stage(
    uint32_t st, int tid, int k0, int rowBase, int colBase,
    const bf16* ahi, const bf16* alo, int lda,
    const bf16* bhi, const bf16* blo, int ldb)
{
#pragma unroll
    for (int i = 0; i < 4; i++) {
        int idx = tid + i * 256;
        int r = idx >> 3, ch = idx & 7;
        uint32_t so = SWZ((uint32_t)(r * 128 + ch * 16));
        const size_t ao = (size_t)(rowBase + r) * lda + k0 + ch * 8;
        const size_t bo = (size_t)(colBase + r) * ldb + k0 + ch * 8;
        cp16(st + STG_A_HI + so, ahi + ao);
        cp16(st + STG_A_LO + so, alo + ao);
        cp16(st + STG_B_HI + so, bhi + bo);
        cp16(st + STG_B_LO + so, blo + bo);
    }
}

// EPI 0: fp32 C (scaled by alpha).  EPI 1: bf16 hi/lo plane outputs.
template<int EPI>
__device__ void hmma_gemm(const bf16* __restrict__ ahi, const bf16* __restrict__ alo, int lda,
                          const bf16* __restrict__ bhi, const bf16* __restrict__ blo, int ldb,
                          float* __restrict__ C, bf16* __restrict__ Chi, bf16* __restrict__ Clo,
                          int ldc, int K, float alpha)
{
    const uint32_t sb = smem_u32(dynsmem);
    const int tid = threadIdx.x;
    const int lane = tid & 31, wid = tid >> 5;
    const int warpM = wid >> 2, warpN = wid & 3;     // 2 x 4 warp grid
    const int rowBase = blockIdx.y * BM, colBase = blockIdx.x * BN;

    float acc[4][4][4];
#pragma unroll
    for (int mf = 0; mf < 4; mf++)
#pragma unroll
        for (int nf = 0; nf < 4; nf++)
#pragma unroll
            for (int c = 0; c < 4; c++) acc[mf][nf][c] = 0.f;

    const int KI = K / BK;
    load_stage(sb, tid, 0, rowBase, colBase, ahi, alo, lda, bhi, blo, ldb);
    cp_commit();
    load_stage(sb + STG_STRIDE, tid, BK, rowBase, colBase, ahi, alo, lda, bhi, blo, ldb);
    cp_commit();

    for (int it = 0; it < KI; it++) {
        cp_wait<1>();
        __syncthreads();
        const uint32_t st = sb + (it & 1) * STG_STRIDE;

#pragma unroll
        for (int ks = 0; ks < 4; ks++) {
            uint32_t ah[4][4], al[4][4];
            uint32_t bh[4][2], bl[4][2];
            const int kk = ks * 16 + (lane >> 4) * 8;
#pragma unroll
            for (int mf = 0; mf < 4; mf++) {
                int row = warpM * 64 + mf * 16 + (lane & 15);
                uint32_t addr = st + SWZ((uint32_t)(row * 128 + kk * 2));
                ldsm4(ah[mf], addr + STG_A_HI);
                ldsm4(al[mf], addr + STG_A_LO);
            }
#pragma unroll
            for (int nb = 0; nb < 2; nb++) {
                int nrow = warpN * 32 + nb * 16 + (lane & 15);
                uint32_t addr = st + SWZ((uint32_t)(nrow * 128 + kk * 2));
                uint32_t t[4];
                ldsm4(t, addr + STG_B_HI);
                bh[nb*2][0] = t[0]; bh[nb*2][1] = t[2];
                bh[nb*2+1][0] = t[1]; bh[nb*2+1][1] = t[3];
                ldsm4(t, addr + STG_B_LO);
                bl[nb*2][0] = t[0]; bl[nb*2][1] = t[2];
                bl[nb*2+1][0] = t[1]; bl[nb*2+1][1] = t[3];
            }
            // product-major: 16 independent accumulators between same-acc reuses
#pragma unroll
            for (int mf = 0; mf < 4; mf++)
#pragma unroll
                for (int nf = 0; nf < 4; nf++) mma16816(acc[mf][nf], ah[mf], bh[nf]);
#pragma unroll
            for (int mf = 0; mf < 4; mf++)
#pragma unroll
                for (int nf = 0; nf < 4; nf++) mma16816(acc[mf][nf], ah[mf], bl[nf]);
#pragma unroll
            for (int mf = 0; mf < 4; mf++)
#pragma unroll
                for (int nf = 0; nf < 4; nf++) mma16816(acc[mf][nf], al[mf], bh[nf]);
        }
        __syncthreads();
        if (it + 2 < KI)
            load_stage(sb + (it & 1) * STG_STRIDE, tid, (it + 2) * BK,
                       rowBase, colBase, ahi, alo, lda, bhi, blo, ldb);
        cp_commit();
    }
    cp_wait<0>();

#pragma unroll
    for (int mf = 0; mf < 4; mf++) {
        int row0 = rowBase + warpM * 64 + mf * 16 + (lane >> 2);
#pragma unroll
        for (int nf = 0; nf < 4; nf++) {
            int col = colBase + warpN * 32 + nf * 8 + (lane & 3) * 2;
            if (EPI == 0) {
                float2 v0 = {alpha * acc[mf][nf][0], alpha * acc[mf][nf][1]};
                float2 v1 = {alpha * acc[mf][nf][2], alpha * acc[mf][nf][3]};
                *(float2*)(C + (size_t)row0 * ldc + col) = v0;
                *(float2*)(C + (size_t)(row0 + 8) * ldc + col) = v1;
            } else {
#pragma unroll
                for (int half = 0; half < 2; half++) {
                    size_t o = (size_t)(row0 + half * 8) * ldc + col;
                    float v0 = acc[mf][nf][half * 2], v1 = acc[mf][nf][half * 2 + 1];
                    bf16 h0 = __float2bfloat16(v0), h1 = __float2bfloat16(v1);
                    bf16 l0 = __float2bfloat16(v0 - __bfloat162float(h0));
                    bf16 l1 = __float2bfloat16(v1 - __bfloat162float(h1));
                    uint32_t hp = (uint32_t)__bfloat16_as_ushort(h0) | ((uint32_t)__bfloat16_as_ushort(h1) << 16);
                    uint32_t lp = (uint32_t)__bfloat16_as_ushort(l0) | ((uint32_t)__bfloat16_as_ushort(l1) << 16);
                    *(uint32_t*)(Chi + o) = hp;
                    *(uint32_t*)(Clo + o) = lp;
                }
            }
        }
    }
}

// ---------------- GEMM wrappers ----------------
__global__ __launch_bounds__(256, 1) void k_gemm_plain(
    const bf16* ahi, const bf16* alo, int lda,
    const bf16* bhi, const bf16* blo, int ldb,
    float* C, int ldc, int K, float alpha)
{
    hmma_gemm<0>(ahi, alo, lda, bhi, blo, ldb, C, nullptr, nullptr, ldc, K, alpha);
}

__global__ __launch_bounds__(256, 1) void k_gemm_scores(
    const bf16* qhi, const bf16* qlo, const bf16* khi, const bf16* klo, float* W)
{
    if (blockIdx.x > blockIdx.y) return;     // causal: fully-masked tile
    const int bh = blockIdx.z, b = bh / NHEAD, h = bh % NHEAD;
    size_t qa = (size_t)b * SEQ * DMODEL + (size_t)h * HD;
    size_t ka = (size_t)b * SEQ * HD;
    hmma_gemm<0>(qhi + qa, qlo + qa, DMODEL, khi + ka, klo + ka, HD,
                 W + (size_t)bh * SEQ * SEQ, nullptr, nullptr, SEQ, HD, 0.0625f);
}

__global__ __launch_bounds__(256, 1) void k_gemm_pv(
    const bf16* phi, const bf16* plo, const bf16* vthi, const bf16* vtlo,
    bf16* ahi_out, bf16* alo_out)
{
    const int bh = blockIdx.z, b = bh / NHEAD, h = bh % NHEAD;
    size_t pa = (size_t)bh * SEQ * SEQ;
    size_t va = (size_t)b * HD * SEQ;
    int kmax = (blockIdx.y + 1) * BM;        // causal clamp
    size_t co = (size_t)b * SEQ * DMODEL + (size_t)h * HD;
    hmma_gemm<1>(phi + pa, plo + pa, SEQ, vthi + va, vtlo + va, SEQ,
                 nullptr, ahi_out + co, alo_out + co, DMODEL, kmax, 1.0f);
}

// ---------------- elementwise fp32 -> bf16 hi/lo split ----------------
__global__ __launch_bounds__(256) void k_cvt(const float4* __restrict__ x,
                                             uint2* __restrict__ hi, uint2* __restrict__ lo, int n4)
{
    int i = blockIdx.x * 256 + threadIdx.x;
    if (i >= n4) return;
    float4 v = x[i];
    bf16 h0 = __float2bfloat16(v.x), h1 = __float2bfloat16(v.y);
    bf16 h2 = __float2bfloat16(v.z), h3 = __float2bfloat16(v.w);
    bf16 g0 = __float2bfloat16(v.x - __bfloat162float(h0));
    bf16 g1 = __float2bfloat16(v.y - __bfloat162float(h1));
    bf16 g2 = __float2bfloat16(v.z - __bfloat162float(h2));
    bf16 g3 = __float2bfloat16(v.w - __bfloat162float(h3));
    uint2 H, L;
    H.x = (uint32_t)__bfloat16_as_ushort(h0) | ((uint32_t)__bfloat16_as_ushort(h1) << 16);
    H.y = (uint32_t)__bfloat16_as_ushort(h2) | ((uint32_t)__bfloat16_as_ushort(h3) << 16);
    L.x = (uint32_t)__bfloat16_as_ushort(g0) | ((uint32_t)__bfloat16_as_ushort(g1) << 16);
    L.y = (uint32_t)__bfloat16_as_ushort(g2) | ((uint32_t)__bfloat16_as_ushort(g3) << 16);
    hi[i] = H;
    lo[i] = L;
}

// ---------------- RoPE (fp32 in) -> bf16 hi/lo planes ----------------
__global__ __launch_bounds__(256) void k_rope_cvt(const int* __restrict__ pos) {
    int idx = blockIdx.x * 256 + threadIdx.x;
    const int total = ROWS * (NHEAD + 1) * 128;
    if (idx >= total) return;
    int j = idx & 127;
    int rest = idx >> 7;
    int slot = rest % (NHEAD + 1);
    int row = rest / (NHEAD + 1);
    float p = (float)pos[row];
    float f = exp2f(-((float)(2 * j) * (1.0f / (float)HD)) * 13.287712379549449f);
    float sv, cv;
    sincosf(p * f, &sv, &cv);
    float x1, x2;
    size_t o;
    if (slot < NHEAD) { o = (size_t)row * DMODEL + slot * HD + j; x1 = g_q[o]; x2 = g_q[o + 128]; }
    else              { o = (size_t)row * HD + j;                 x1 = g_k[o]; x2 = g_k[o + 128]; }
    float y1 = x1 * cv - x2 * sv;
    float y2 = x2 * cv + x1 * sv;
    bf16 h1 = __float2bfloat16(y1), h2 = __float2bfloat16(y2);
    bf16 l1 = __float2bfloat16(y1 - __bfloat162float(h1));
    bf16 l2 = __float2bfloat16(y2 - __bfloat162float(h2));
    if (slot < NHEAD) {
        s_qhi[o] = h1; s_qlo[o] = l1; s_qhi[o + 128] = h2; s_qlo[o + 128] = l2;
    } else {
        s_khi[o] = h1; s_klo[o] = l1; s_khi[o + 128] = h2; s_klo[o + 128] = l2;
    }
}

// ---------------- V transpose + split: g_v[b,k,n] -> vt[b,n,k] ----------------
__global__ void k_vt() {
    __shared__ float t[32][33];
    int b = blockIdx.z;
    int k0 = blockIdx.x * 32, n0 = blockIdx.y * 32;
    int tx = threadIdx.x, ty = threadIdx.y;   // 32 x 8
#pragma unroll
    for (int i = 0; i < 32; i += 8)
        t[ty + i][tx] = g_v[((size_t)(b * SEQ + k0 + ty + i)) * HD + n0 + tx];
    __syncthreads();
#pragma unroll
    for (int i = 0; i < 32; i += 8) {
        float v = t[tx][ty + i];
        bf16 h = __float2bfloat16(v);
        bf16 l = __float2bfloat16(v - __bfloat162float(h));
        size_t o = ((size_t)(b * HD + n0 + ty + i)) * SEQ + k0 + tx;
        s_vthi[o] = h;
        s_vtlo[o] = l;
    }
}

// ---------------- causal softmax (in-place fp32) + bf16 hi/lo plane emit ----------------
__global__ __launch_bounds__(256) void k_softmax(float* __restrict__ w) {
    const int row = blockIdx.x;               // bh*SEQ + q
    const int q = row & (SEQ - 1);
    float* p = w + (size_t)row * SEQ;
    const size_t pb = (size_t)row * SEQ;
    const int len = q + 1;
    const int tid = threadIdx.x;
    __shared__ float red[256];

    float vals[SEQ / 256];
    int cnt = 0;
    float m = -3.4e38f;
    for (int i = tid; i < len; i += 256) {
        float x = p[i];
        vals[cnt++] = x;
        m = fmaxf(m, x);
    }
    red[tid] = m;
    __syncthreads();
#pragma unroll
    for (int s2 = 128; s2 > 0; s2 >>= 1) {
        if (tid < s2) red[tid] = fmaxf(red[tid], red[tid + s2]);
        __syncthreads();
    }
    m = red[0];
    __syncthreads();

    float sum = 0.f;
    for (int c = 0; c < cnt; c++) {
        vals[c] = expf(vals[c] - m);
        sum += vals[c];
    }
    red[tid] = sum;
    __syncthreads();
#pragma unroll
    for (int s2 = 128; s2 > 0; s2 >>= 1) {
        if (tid < s2) red[tid] += red[tid + s2];
        __syncthreads();
    }
    float inv = 1.0f / red[0];

    cnt = 0;
    for (int i = tid; i < len; i += 256) {
        float v = vals[cnt++] * inv;
        p[i] = v;
        bf16 h = __float2bfloat16(v);
        s_phi[pb + i] = h;
        s_plo[pb + i] = __float2bfloat16(v - __bfloat162float(h));
    }
    // fp32 weights: full zero tail (required output)
    for (int i = len + tid; i < SEQ; i += 256) p[i] = 0.0f;
    // bf16 P planes: PV only reads up to the 128-aligned diagonal boundary
    const int kmax = (len + 127) & ~127;
    const bf16 z = __float2bfloat16(0.0f);
    for (int i = len + tid; i < kmax; i += 256) {
        s_phi[pb + i] = z;
        s_plo[pb + i] = z;
    }
}

// ---------------- launch ----------------
static void* sym(const void* s) { void* p = nullptr; cudaGetSymbolAddress(&p, s); return p; }

extern "C" void kernel_launch(void* const* d_in, const int* in_sizes, int n_in,
                              void* d_out, int out_size) {
    const float* hidden = (const float*)d_in[0];
    const int*   pos    = (const int*)d_in[2];
    const float* Wq     = (const float*)d_in[3];
    const float* Wk     = (const float*)d_in[4];
    const float* Wv     = (const float*)d_in[5];
    const float* Wo     = (const float*)d_in[6];

    float* out      = (float*)d_out;
    float* weights  = out + (size_t)ROWS * DMODEL;   // (B, H, S, S)

    cudaFuncSetAttribute(k_gemm_plain,  cudaFuncAttributeMaxDynamicSharedMemorySize, SMEM_BYTES);
    cudaFuncSetAttribute(k_gemm_scores, cudaFuncAttributeMaxDynamicSharedMemorySize, SMEM_BYTES);
    cudaFuncSetAttribute(k_gemm_pv,     cudaFuncAttributeMaxDynamicSharedMemorySize, SMEM_BYTES);

    bf16 *xhi = (bf16*)sym(s_xhi),  *xlo = (bf16*)sym(s_xlo);
    bf16 *wqh = (bf16*)sym(s_wqhi), *wql = (bf16*)sym(s_wqlo);
    bf16 *wkh = (bf16*)sym(s_wkhi), *wkl = (bf16*)sym(s_wklo);
    bf16 *wvh = (bf16*)sym(s_wvhi), *wvl = (bf16*)sym(s_wvlo);
    bf16 *woh = (bf16*)sym(s_wohi), *wol = (bf16*)sym(s_wolo);
    bf16 *qhi = (bf16*)sym(s_qhi),  *qlo = (bf16*)sym(s_qlo);
    bf16 *khi = (bf16*)sym(s_khi),  *klo = (bf16*)sym(s_klo);
    bf16 *vth = (bf16*)sym(s_vthi), *vtl = (bf16*)sym(s_vtlo);
    bf16 *phi = (bf16*)sym(s_phi),  *plo = (bf16*)sym(s_plo);
    bf16 *ahi = (bf16*)sym(s_ahi),  *alo = (bf16*)sym(s_alo);
    float *gq = (float*)sym(g_q), *gk = (float*)sym(g_k);
    float *gv = (float*)sym(g_v);

    // 1. split inputs/weights into bf16 hi/lo planes
    {
        int n4 = ROWS * DMODEL / 4;
        k_cvt<<<(n4 + 255) / 256, 256>>>((const float4*)hidden, (uint2*)xhi, (uint2*)xlo, n4);
        n4 = DMODEL * DMODEL / 4;
        k_cvt<<<(n4 + 255) / 256, 256>>>((const float4*)Wq, (uint2*)wqh, (uint2*)wql, n4);
        k_cvt<<<(n4 + 255) / 256, 256>>>((const float4*)Wo, (uint2*)woh, (uint2*)wol, n4);
        n4 = HD * DMODEL / 4;
        k_cvt<<<(n4 + 255) / 256, 256>>>((const float4*)Wk, (uint2*)wkh, (uint2*)wkl, n4);
        k_cvt<<<(n4 + 255) / 256, 256>>>((const float4*)Wv, (uint2*)wvh, (uint2*)wvl, n4);
    }

    // 2. projections (HMMA)
    k_gemm_plain<<<dim3(DMODEL / BN, ROWS / BM), 256, SMEM_BYTES>>>(xhi, xlo, DMODEL, wqh, wql, DMODEL, gq, DMODEL, DMODEL, 1.0f);
    k_gemm_plain<<<dim3(HD / BN, ROWS / BM),     256, SMEM_BYTES>>>(xhi, xlo, DMODEL, wkh, wkl, DMODEL, gk, HD, DMODEL, 1.0f);
    k_gemm_plain<<<dim3(HD / BN, ROWS / BM),     256, SMEM_BYTES>>>(xhi, xlo, DMODEL, wvh, wvl, DMODEL, gv, HD, DMODEL, 1.0f);

    // 3. RoPE -> bf16 planes ; V transpose -> bf16 planes
    {
        int total = ROWS * (NHEAD + 1) * 128;
        k_rope_cvt<<<(total + 255) / 256, 256>>>(pos);
    }
    k_vt<<<dim3(SEQ / 32, HD / 32, BATCH), dim3(32, 8)>>>();

    // 4. scores (causal tile skip) -> weights fp32 region of d_out
    k_gemm_scores<<<dim3(SEQ / BN, SEQ / BM, BH), 256, SMEM_BYTES>>>(qhi, qlo, khi, klo, weights);

    // 5. softmax in place + emit P bf16 planes
    k_softmax<<<BH * SEQ, 256>>>(weights);

    // 6. P @ V  (causal K clamp) -> bf16 planes for Wo GEMM directly
    k_gemm_pv<<<dim3(HD / BN, SEQ / BM, BH), 256, SMEM_BYTES>>>(phi, plo, vth, vtl, ahi, alo);

    // 7. output projection
    k_gemm_plain<<<dim3(DMODEL / BN, ROWS / BM), 256, SMEM_BYTES>>>(ahi, alo, DMODEL, woh, wol, DMODEL, out, DMODEL, DMODEL, 1.0f);
}

// round 6
// speedup vs baseline: 2.0129x; 1.3304x over previous
#include <cuda_runtime.h>
#include <cuda_fp16.h>
#include <cstdint>

#define SEQ    2048
#define DMODEL 2048
#define NHEAD  8
#define HD     256
#define BATCH  2
#define BH     (BATCH*NHEAD)
#define ROWS   (BATCH*SEQ)          // 4096

typedef __half h16;

// ---------------- scratch (device globals; alloc-guard compliant) ----------------
__device__ __align__(256) h16 s_xhi[(size_t)ROWS*DMODEL],   s_xlo[(size_t)ROWS*DMODEL];
__device__ __align__(256) h16 s_wq[(size_t)DMODEL*DMODEL];
__device__ __align__(256) h16 s_wk[(size_t)HD*DMODEL];
__device__ __align__(256) h16 s_wv[(size_t)HD*DMODEL];
__device__ __align__(256) h16 s_wo[(size_t)DMODEL*DMODEL];
__device__ __align__(256) h16 s_qhi[(size_t)ROWS*DMODEL],   s_qlo[(size_t)ROWS*DMODEL];
__device__ __align__(256) h16 s_kh[(size_t)ROWS*HD];
__device__ __align__(256) h16 s_vt[(size_t)BATCH*HD*SEQ];
__device__ __align__(256) h16 s_phi[(size_t)BH*SEQ*SEQ],    s_plo[(size_t)BH*SEQ*SEQ];
__device__ __align__(256) h16 s_ahi[(size_t)ROWS*DMODEL],   s_alo[(size_t)ROWS*DMODEL];
__device__ __align__(16) float g_q[(size_t)ROWS*DMODEL];
__device__ __align__(16) float g_k[(size_t)ROWS*HD];
__device__ __align__(16) float g_v[(size_t)ROWS*HD];

// ---------------- helpers ----------------
__device__ __forceinline__ uint32_t smem_u32(const void* p) {
    uint32_t a;
    asm("{ .reg .u64 t; cvta.to.shared.u64 t, %1; cvt.u32.u64 %0, t; }" : "=r"(a) : "l"(p));
    return a;
}
#define SWZ(o) ((o) ^ (((o) >> 3) & 0x70))

__device__ __forceinline__ void cp16(uint32_t saddr, const void* gaddr) {
    asm volatile("cp.async.cg.shared.global [%0], [%1], 16;" :: "r"(saddr), "l"(gaddr));
}
__device__ __forceinline__ void cp_commit() { asm volatile("cp.async.commit_group;"); }
template<int N> __device__ __forceinline__ void cp_wait() {
    asm volatile("cp.async.wait_group %0;" :: "n"(N));
}
__device__ __forceinline__ void ldsm4(uint32_t* r, uint32_t addr) {
    asm volatile("ldmatrix.sync.aligned.m8n8.x4.shared.b16 {%0,%1,%2,%3}, [%4];"
                 : "=r"(r[0]), "=r"(r[1]), "=r"(r[2]), "=r"(r[3]) : "r"(addr));
}
__device__ __forceinline__ void mma16816(float* c, const uint32_t* a, const uint32_t* b) {
    asm volatile(
        "mma.sync.aligned.m16n8k16.row.col.f32.f16.f16.f32 "
        "{%0,%1,%2,%3}, {%4,%5,%6,%7}, {%8,%9}, {%0,%1,%2,%3};"
        : "+f"(c[0]), "+f"(c[1]), "+f"(c[2]), "+f"(c[3])
        : "r"(a[0]), "r"(a[1]), "r"(a[2]), "r"(a[3]), "r"(b[0]), "r"(b[1]));
}
__device__ __forceinline__ void split2(float v, h16& hi, h16& lo) {
    hi = __float2half_rn(v);
    lo = __float2half_rn(v - __half2float(hi));
}

// ---------------- HMMA GEMM: C[M,N] = alpha * A[M,K] @ B[N,K]^T
//   A split fp16 (hi+lo, exact), B rounded fp16 — 2 products per fragment.
#define BM 128
#define BN 128
#define BK 64
#define STG_A_HI 0
#define STG_A_LO 16384
#define STG_B    32768
#define STG_STRIDE 49152
#define SMEM_BYTES (2*STG_STRIDE)   // 98304

extern __shared__ char dynsmem[];

__device__ __forceinline__ void load_stage(
    uint32_t st, int tid, int k0, int rowBase, int colBase,
    const h16* ahi, const h16* alo, int lda,
    const h16* b, int ldb)
{
#pragma unroll
    for (int i = 0; i < 4; i++) {
        int idx = tid + i * 256;
        int r = idx >> 3, ch = idx & 7;
        uint32_t so = SWZ((uint32_t)(r * 128 + ch * 16));
        const size_t ao = (size_t)(rowBase + r) * lda + k0 + ch * 8;
        const size_t bo = (size_t)(colBase + r) * ldb + k0 + ch * 8;
        cp16(st + STG_A_HI + so, ahi + ao);
        cp16(st + STG_A_LO + so, alo + ao);
        cp16(st + STG_B    + so, b + bo);
    }
}

// EPI 0: fp32 C (scaled by alpha).  EPI 1: fp16 hi/lo plane outputs.
template<int EPI>
__device__ void hmma_gemm(const h16* __restrict__ ahi, const h16* __restrict__ alo, int lda,
                          const h16* __restrict__ b, int ldb,
                          float* __restrict__ C, h16* __restrict__ Chi, h16* __restrict__ Clo,
                          int ldc, int K, float alpha)
{
    const uint32_t sb = smem_u32(dynsmem);
    const int tid = threadIdx.x;
    const int lane = tid & 31, wid = tid >> 5;
    const int warpM = wid >> 2, warpN = wid & 3;     // 2 x 4 warp grid
    const int rowBase = blockIdx.y * BM, colBase = blockIdx.x * BN;

    float acc[4][4][4];
#pragma unroll
    for (int mf = 0; mf < 4; mf++)
#pragma unroll
        for (int nf = 0; nf < 4; nf++)
#pragma unroll
            for (int c = 0; c < 4; c++) acc[mf][nf][c] = 0.f;

    const int KI = K / BK;
    load_stage(sb, tid, 0, rowBase, colBase, ahi, alo, lda, b, ldb);
    cp_commit();
    load_stage(sb + STG_STRIDE, tid, BK, rowBase, colBase, ahi, alo, lda, b, ldb);
    cp_commit();

    for (int it = 0; it < KI; it++) {
        cp_wait<1>();
        __syncthreads();
        const uint32_t st = sb + (it & 1) * STG_STRIDE;

#pragma unroll
        for (int ks = 0; ks < 4; ks++) {
            uint32_t ah[4][4], al[4][4];
            uint32_t bf[4][2];
            const int kk = ks * 16 + (lane >> 4) * 8;
#pragma unroll
            for (int mf = 0; mf < 4; mf++) {
                int row = warpM * 64 + mf * 16 + (lane & 15);
                uint32_t addr = st + SWZ((uint32_t)(row * 128 + kk * 2));
                ldsm4(ah[mf], addr + STG_A_HI);
                ldsm4(al[mf], addr + STG_A_LO);
            }
#pragma unroll
            for (int nb = 0; nb < 2; nb++) {
                int nrow = warpN * 32 + nb * 16 + (lane & 15);
                uint32_t addr = st + SWZ((uint32_t)(nrow * 128 + kk * 2));
                uint32_t t[4];
                ldsm4(t, addr + STG_B);
                bf[nb*2][0] = t[0]; bf[nb*2][1] = t[2];
                bf[nb*2+1][0] = t[1]; bf[nb*2+1][1] = t[3];
            }
            // product-major: 16 independent accumulators between same-acc reuses
#pragma unroll
            for (int mf = 0; mf < 4; mf++)
#pragma unroll
                for (int nf = 0; nf < 4; nf++) mma16816(acc[mf][nf], ah[mf], bf[nf]);
#pragma unroll
            for (int mf = 0; mf < 4; mf++)
#pragma unroll
                for (int nf = 0; nf < 4; nf++) mma16816(acc[mf][nf], al[mf], bf[nf]);
        }
        __syncthreads();
        if (it + 2 < KI)
            load_stage(sb + (it & 1) * STG_STRIDE, tid, (it + 2) * BK,
                       rowBase, colBase, ahi, alo, lda, b, ldb);
        cp_commit();
    }
    cp_wait<0>();

#pragma unroll
    for (int mf = 0; mf < 4; mf++) {
        int row0 = rowBase + warpM * 64 + mf * 16 + (lane >> 2);
#pragma unroll
        for (int nf = 0; nf < 4; nf++) {
            int col = colBase + warpN * 32 + nf * 8 + (lane & 3) * 2;
            if (EPI == 0) {
                float2 v0 = {alpha * acc[mf][nf][0], alpha * acc[mf][nf][1]};
                float2 v1 = {alpha * acc[mf][nf][2], alpha * acc[mf][nf][3]};
                *(float2*)(C + (size_t)row0 * ldc + col) = v0;
                *(float2*)(C + (size_t)(row0 + 8) * ldc + col) = v1;
            } else {
#pragma unroll
                for (int half = 0; half < 2; half++) {
                    size_t o = (size_t)(row0 + half * 8) * ldc + col;
                    float v0 = acc[mf][nf][half * 2], v1 = acc[mf][nf][half * 2 + 1];
                    h16 h0, l0, h1, l1;
                    split2(v0, h0, l0);
                    split2(v1, h1, l1);
                    uint32_t hp = (uint32_t)__half_as_ushort(h0) | ((uint32_t)__half_as_ushort(h1) << 16);
                    uint32_t lp = (uint32_t)__half_as_ushort(l0) | ((uint32_t)__half_as_ushort(l1) << 16);
                    *(uint32_t*)(Chi + o) = hp;
                    *(uint32_t*)(Clo + o) = lp;
                }
            }
        }
    }
}

// ---------------- GEMM wrappers ----------------
__global__ __launch_bounds__(256, 1) void k_gemm_plain(
    const h16* ahi, const h16* alo, int lda,
    const h16* b, int ldb,
    float* C, int ldc, int K, float alpha)
{
    hmma_gemm<0>(ahi, alo, lda, b, ldb, C, nullptr, nullptr, ldc, K, alpha);
}

__global__ __launch_bounds__(256, 1) void k_gemm_scores(
    const h16* qhi, const h16* qlo, const h16* kh, float* W)
{
    if (blockIdx.x > blockIdx.y) return;     // causal: fully-masked tile
    const int bh = blockIdx.z, b = bh / NHEAD, h = bh % NHEAD;
    size_t qa = (size_t)b * SEQ * DMODEL + (size_t)h * HD;
    size_t ka = (size_t)b * SEQ * HD;
    hmma_gemm<0>(qhi + qa, qlo + qa, DMODEL, kh + ka, HD,
                 W + (size_t)bh * SEQ * SEQ, nullptr, nullptr, SEQ, HD, 0.0625f);
}

__global__ __launch_bounds__(256, 1) void k_gemm_pv(
    const h16* phi, const h16* plo, const h16* vt,
    h16* ahi_out, h16* alo_out)
{
    const int bh = blockIdx.z, b = bh / NHEAD, h = bh % NHEAD;
    size_t pa = (size_t)bh * SEQ * SEQ;
    size_t va = (size_t)b * HD * SEQ;
    int kmax = (blockIdx.y + 1) * BM;        // causal clamp
    size_t co = (size_t)b * SEQ * DMODEL + (size_t)h * HD;
    hmma_gemm<1>(phi + pa, plo + pa, SEQ, vt + va, SEQ,
                 nullptr, ahi_out + co, alo_out + co, DMODEL, kmax, 1.0f);
}

// ---------------- fp32 -> fp16 hi/lo split (activations) ----------------
__global__ __launch_bounds__(256) void k_cvt_split(const float4* __restrict__ x,
                                                   uint2* __restrict__ hi, uint2* __restrict__ lo, int n4)
{
    int i = blockIdx.x * 256 + threadIdx.x;
    if (i >= n4) return;
    float4 v = x[i];
    h16 h0, l0, h1, l1, h2, l2, h3, l3;
    split2(v.x, h0, l0); split2(v.y, h1, l1);
    split2(v.z, h2, l2); split2(v.w, h3, l3);
    uint2 H, L;
    H.x = (uint32_t)__half_as_ushort(h0) | ((uint32_t)__half_as_ushort(h1) << 16);
    H.y = (uint32_t)__half_as_ushort(h2) | ((uint32_t)__half_as_ushort(h3) << 16);
    L.x = (uint32_t)__half_as_ushort(l0) | ((uint32_t)__half_as_ushort(l1) << 16);
    L.y = (uint32_t)__half_as_ushort(l2) | ((uint32_t)__half_as_ushort(l3) << 16);
    hi[i] = H;
    lo[i] = L;
}

// ---------------- fp32 -> fp16 round (weights) ----------------
__global__ __launch_bounds__(256) void k_cvt_round(const float4* __restrict__ x,
                                                   uint2* __restrict__ out, int n4)
{
    int i = blockIdx.x * 256 + threadIdx.x;
    if (i >= n4) return;
    float4 v = x[i];
    uint2 O;
    O.x = (uint32_t)__half_as_ushort(__float2half_rn(v.x)) | ((uint32_t)__half_as_ushort(__float2half_rn(v.y)) << 16);
    O.y = (uint32_t)__half_as_ushort(__float2half_rn(v.z)) | ((uint32_t)__half_as_ushort(__float2half_rn(v.w)) << 16);
    out[i] = O;
}

// ---------------- RoPE (fp32 in) -> Q fp16 hi/lo, K fp16 single ----------------
__global__ __launch_bounds__(256) void k_rope_cvt(const int* __restrict__ pos) {
    int idx = blockIdx.x * 256 + threadIdx.x;
    const int total = ROWS * (NHEAD + 1) * 128;
    if (idx >= total) return;
    int j = idx & 127;
    int rest = idx >> 7;
    int slot = rest % (NHEAD + 1);
    int row = rest / (NHEAD + 1);
    float p = (float)pos[row];
    float f = exp2f(-((float)(2 * j) * (1.0f / (float)HD)) * 13.287712379549449f);
    float sv, cv;
    sincosf(p * f, &sv, &cv);
    float x1, x2;
    size_t o;
    if (slot < NHEAD) { o = (size_t)row * DMODEL + slot * HD + j; x1 = g_q[o]; x2 = g_q[o + 128]; }
    else              { o = (size_t)row * HD + j;                 x1 = g_k[o]; x2 = g_k[o + 128]; }
    float y1 = x1 * cv - x2 * sv;
    float y2 = x2 * cv + x1 * sv;
    if (slot < NHEAD) {
        h16 h1, l1, h2, l2;
        split2(y1, h1, l1);
        split2(y2, h2, l2);
        s_qhi[o] = h1; s_qlo[o] = l1; s_qhi[o + 128] = h2; s_qlo[o + 128] = l2;
    } else {
        s_kh[o] = __float2half_rn(y1);
        s_kh[o + 128] = __float2half_rn(y2);
    }
}

// ---------------- V transpose + round: g_v[b,k,n] -> vt[b,n,k] fp16 ----------------
__global__ void k_vt() {
    __shared__ float t[32][33];
    int b = blockIdx.z;
    int k0 = blockIdx.x * 32, n0 = blockIdx.y * 32;
    int tx = threadIdx.x, ty = threadIdx.y;   // 32 x 8
#pragma unroll
    for (int i = 0; i < 32; i += 8)
        t[ty + i][tx] = g_v[((size_t)(b * SEQ + k0 + ty + i)) * HD + n0 + tx];
    __syncthreads();
#pragma unroll
    for (int i = 0; i < 32; i += 8) {
        float v = t[tx][ty + i];
        size_t o = ((size_t)(b * HD + n0 + ty + i)) * SEQ + k0 + tx;
        s_vt[o] = __float2half_rn(v);
    }
}

// ---------------- causal softmax (in-place fp32) + fp16 hi/lo P emit ----------------
__global__ __launch_bounds__(256) void k_softmax(float* __restrict__ w) {
    const int row = blockIdx.x;               // bh*SEQ + q
    const int q = row & (SEQ - 1);
    float* p = w + (size_t)row * SEQ;
    const size_t pb = (size_t)row * SEQ;
    const int len = q + 1;
    const int tid = threadIdx.x;
    __shared__ float red[256];

    float vals[SEQ / 256];
    int cnt = 0;
    float m = -3.4e38f;
    for (int i = tid; i < len; i += 256) {
        float x = p[i];
        vals[cnt++] = x;
        m = fmaxf(m, x);
    }
    red[tid] = m;
    __syncthreads();
#pragma unroll
    for (int s2 = 128; s2 > 0; s2 >>= 1) {
        if (tid < s2) red[tid] = fmaxf(red[tid], red[tid + s2]);
        __syncthreads();
    }
    m = red[0];
    __syncthreads();

    float sum = 0.f;
    for (int c = 0; c < cnt; c++) {
        vals[c] = expf(vals[c] - m);
        sum += vals[c];
    }
    red[tid] = sum;
    __syncthreads();
#pragma unroll
    for (int s2 = 128; s2 > 0; s2 >>= 1) {
        if (tid < s2) red[tid] += red[tid + s2];
        __syncthreads();
    }
    float inv = 1.0f / red[0];

    cnt = 0;
    for (int i = tid; i < len; i += 256) {
        float v = vals[cnt++] * inv;
        p[i] = v;
        h16 h, l;
        split2(v, h, l);
        s_phi[pb + i] = h;
        s_plo[pb + i] = l;
    }
    // fp32 weights: full zero tail (required output)
    for (int i = len + tid; i < SEQ; i += 256) p[i] = 0.0f;
    // fp16 P planes: PV only reads up to the 128-aligned diagonal boundary
    const int kmax = (len + 127) & ~127;
    const h16 z = __float2half_rn(0.0f);
    for (int i = len + tid; i < kmax; i += 256) {
        s_phi[pb + i] = z;
        s_plo[pb + i] = z;
    }
}

// ---------------- launch ----------------
static void* sym(const void* s) { void* p = nullptr; cudaGetSymbolAddress(&p, s); return p; }

extern "C" void kernel_launch(void* const* d_in, const int* in_sizes, int n_in,
                              void* d_out, int out_size) {
    const float* hidden = (const float*)d_in[0];
    const int*   pos    = (const int*)d_in[2];
    const float* Wq     = (const float*)d_in[3];
    const float* Wk     = (const float*)d_in[4];
    const float* Wv     = (const float*)d_in[5];
    const float* Wo     = (const float*)d_in[6];

    float* out      = (float*)d_out;
    float* weights  = out + (size_t)ROWS * DMODEL;   // (B, H, S, S)

    cudaFuncSetAttribute(k_gemm_plain,  cudaFuncAttributeMaxDynamicSharedMemorySize, SMEM_BYTES);
    cudaFuncSetAttribute(k_gemm_scores, cudaFuncAttributeMaxDynamicSharedMemorySize, SMEM_BYTES);
    cudaFuncSetAttribute(k_gemm_pv,     cudaFuncAttributeMaxDynamicSharedMemorySize, SMEM_BYTES);

    h16 *xhi = (h16*)sym(s_xhi), *xlo = (h16*)sym(s_xlo);
    h16 *wq = (h16*)sym(s_wq), *wk = (h16*)sym(s_wk);
    h16 *wv = (h16*)sym(s_wv), *wo = (h16*)sym(s_wo);
    h16 *qhi = (h16*)sym(s_qhi), *qlo = (h16*)sym(s_qlo);
    h16 *kh  = (h16*)sym(s_kh);
    h16 *vt  = (h16*)sym(s_vt);
    h16 *phi = (h16*)sym(s_phi), *plo = (h16*)sym(s_plo);
    h16 *ahi = (h16*)sym(s_ahi), *alo = (h16*)sym(s_alo);
    float *gq = (float*)sym(g_q), *gk = (float*)sym(g_k);
    float *gv = (float*)sym(g_v);

    // 1. split X (activations); round weights
    {
        int n4 = ROWS * DMODEL / 4;
        k_cvt_split<<<(n4 + 255) / 256, 256>>>((const float4*)hidden, (uint2*)xhi, (uint2*)xlo, n4);
        n4 = DMODEL * DMODEL / 4;
        k_cvt_round<<<(n4 + 255) / 256, 256>>>((const float4*)Wq, (uint2*)wq, n4);
        k_cvt_round<<<(n4 + 255) / 256, 256>>>((const float4*)Wo, (uint2*)wo, n4);
        n4 = HD * DMODEL / 4;
        k_cvt_round<<<(n4 + 255) / 256, 256>>>((const float4*)Wk, (uint2*)wk, n4);
        k_cvt_round<<<(n4 + 255) / 256, 256>>>((const float4*)Wv, (uint2*)wv, n4);
    }

    // 2. projections (HMMA fp16 2-product)
    k_gemm_plain<<<dim3(DMODEL / BN, ROWS / BM), 256, SMEM_BYTES>>>(xhi, xlo, DMODEL, wq, DMODEL, gq, DMODEL, DMODEL, 1.0f);
    k_gemm_plain<<<dim3(HD / BN, ROWS / BM),     256, SMEM_BYTES>>>(xhi, xlo, DMODEL, wk, DMODEL, gk, HD, DMODEL, 1.0f);
    k_gemm_plain<<<dim3(HD / BN, ROWS / BM),     256, SMEM_BYTES>>>(xhi, xlo, DMODEL, wv, DMODEL, gv, HD, DMODEL, 1.0f);

    // 3. RoPE -> Q hi/lo, K single ; V transpose -> single
    {
        int total = ROWS * (NHEAD + 1) * 128;
        k_rope_cvt<<<(total + 255) / 256, 256>>>(pos);
    }
    k_vt<<<dim3(SEQ / 32, HD / 32, BATCH), dim3(32, 8)>>>();

    // 4. scores (causal tile skip) -> weights fp32 region of d_out
    k_gemm_scores<<<dim3(SEQ / BN, SEQ / BM, BH), 256, SMEM_BYTES>>>(qhi, qlo, kh, weights);

    // 5. softmax in place + emit P fp16 planes
    k_softmax<<<BH * SEQ, 256>>>(weights);

    // 6. P @ V  (causal K clamp) -> fp16 planes for Wo GEMM directly
    k_gemm_pv<<<dim3(HD / BN, SEQ / BM, BH), 256, SMEM_BYTES>>>(phi, plo, vt, ahi, alo);

    // 7. output projection
    k_gemm_plain<<<dim3(DMODEL / BN, ROWS / BM), 256, SMEM_BYTES>>>(ahi, alo, DMODEL, wo, DMODEL, out, DMODEL, DMODEL, 1.0f);
}